// round 1
// baseline (speedup 1.0000x reference)
#include <cuda_runtime.h>
#include <cstdint>
#include <math.h>

#define BB 32
#define SS 196
#define TT 64
#define HH 1024
#define VV 32000
#define RR 4096   // 4*H

// ---------------- scratch (static device globals; no allocations) ----------------
__device__ float g_M2[(size_t)BB*SS*HH];   // memory @ attn_W      [B*S, H]
__device__ float g_E [(size_t)BB*TT*RR];   // emb gates precompute [B*T, 4H]
__device__ float g_hs[(size_t)TT*BB*HH];   // h_t history          [T, B, H]
__device__ float g_gp[(size_t)8*BB*RR];    // gate partials        [KS=8, B, 4H]
__device__ float g_h [BB*HH];
__device__ float g_c [BB*HH];
__device__ float g_ctx[BB*HH];
__device__ float g_scores[BB*SS];

// ---------------- generic SGEMM: C = A[M,K] @ B[K,N], all row-major ----------------
__global__ __launch_bounds__(256) void sgemm_nn(
    const float* __restrict__ A, const float* __restrict__ Bm,
    float* __restrict__ C, int M, int N, int K)
{
    __shared__ float As[16][128];
    __shared__ float Bs[16][128];
    int tid = threadIdx.x;
    int n0 = blockIdx.x * 128;
    int m0 = blockIdx.y * 128;
    int tx = tid & 15, ty = tid >> 4;
    float acc[8][8];
    #pragma unroll
    for (int i = 0; i < 8; i++)
        #pragma unroll
        for (int j = 0; j < 8; j++) acc[i][j] = 0.f;

    for (int k0 = 0; k0 < K; k0 += 16) {
        #pragma unroll
        for (int it = 0; it < 2; it++) {
            int idx = tid + it * 256;
            int row = idx >> 2, c4 = idx & 3;
            float4 v = *(const float4*)(A + (size_t)(m0 + row) * K + k0 + c4 * 4);
            As[c4*4+0][row] = v.x; As[c4*4+1][row] = v.y;
            As[c4*4+2][row] = v.z; As[c4*4+3][row] = v.w;
        }
        #pragma unroll
        for (int it = 0; it < 2; it++) {
            int idx = tid + it * 256;
            int row = idx >> 5, c4 = idx & 31;
            float4 v = *(const float4*)(Bm + (size_t)(k0 + row) * N + n0 + c4 * 4);
            *(float4*)&Bs[row][c4*4] = v;
        }
        __syncthreads();
        #pragma unroll
        for (int kk = 0; kk < 16; kk++) {
            float ar[8], br[8];
            *(float4*)&ar[0] = *(const float4*)&As[kk][ty*8];
            *(float4*)&ar[4] = *(const float4*)&As[kk][ty*8+4];
            *(float4*)&br[0] = *(const float4*)&Bs[kk][tx*8];
            *(float4*)&br[4] = *(const float4*)&Bs[kk][tx*8+4];
            #pragma unroll
            for (int i = 0; i < 8; i++)
                #pragma unroll
                for (int j = 0; j < 8; j++) acc[i][j] += ar[i] * br[j];
        }
        __syncthreads();
    }
    #pragma unroll
    for (int i = 0; i < 8; i++) {
        float* cp = C + (size_t)(m0 + ty*8 + i) * N + n0 + tx*8;
        *(float4*)(cp)   = make_float4(acc[i][0], acc[i][1], acc[i][2], acc[i][3]);
        *(float4*)(cp+4) = make_float4(acc[i][4], acc[i][5], acc[i][6], acc[i][7]);
    }
}

// ---- SGEMM: C = A[M,K] @ Bt[N,ldb]^T (first K cols of Bt used); optional row gather
//      on A (A_row = gatherTab + gatherIdx[m]*K), optional "logits" epilogue:
//      row m encodes (t*32+b); written to C[(b*T+t)*N + n] + bias[n].
__global__ __launch_bounds__(256) void sgemm_nt(
    const float* __restrict__ A, const float* __restrict__ Bt,
    float* __restrict__ C, int M, int N, int K, int ldb,
    const int* __restrict__ gatherIdx, const float* __restrict__ gatherTab,
    const float* __restrict__ bias, int logits_mode)
{
    __shared__ float As[16][128];
    __shared__ float Bs[16][128];
    int tid = threadIdx.x;
    int n0 = blockIdx.x * 128;
    int m0 = blockIdx.y * 128;
    int tx = tid & 15, ty = tid >> 4;
    float acc[8][8];
    #pragma unroll
    for (int i = 0; i < 8; i++)
        #pragma unroll
        for (int j = 0; j < 8; j++) acc[i][j] = 0.f;

    for (int k0 = 0; k0 < K; k0 += 16) {
        #pragma unroll
        for (int it = 0; it < 2; it++) {
            int idx = tid + it * 256;
            int row = idx >> 2, c4 = idx & 3;
            const float* arow = gatherIdx
                ? (gatherTab + (size_t)gatherIdx[m0 + row] * K)
                : (A + (size_t)(m0 + row) * K);
            float4 v = *(const float4*)(arow + k0 + c4 * 4);
            As[c4*4+0][row] = v.x; As[c4*4+1][row] = v.y;
            As[c4*4+2][row] = v.z; As[c4*4+3][row] = v.w;
        }
        #pragma unroll
        for (int it = 0; it < 2; it++) {
            int idx = tid + it * 256;
            int row = idx >> 2, c4 = idx & 3;   // row = n index, c4 = k quad
            float4 v = *(const float4*)(Bt + (size_t)(n0 + row) * ldb + k0 + c4 * 4);
            Bs[c4*4+0][row] = v.x; Bs[c4*4+1][row] = v.y;
            Bs[c4*4+2][row] = v.z; Bs[c4*4+3][row] = v.w;
        }
        __syncthreads();
        #pragma unroll
        for (int kk = 0; kk < 16; kk++) {
            float ar[8], br[8];
            *(float4*)&ar[0] = *(const float4*)&As[kk][ty*8];
            *(float4*)&ar[4] = *(const float4*)&As[kk][ty*8+4];
            *(float4*)&br[0] = *(const float4*)&Bs[kk][tx*8];
            *(float4*)&br[4] = *(const float4*)&Bs[kk][tx*8+4];
            #pragma unroll
            for (int i = 0; i < 8; i++)
                #pragma unroll
                for (int j = 0; j < 8; j++) acc[i][j] += ar[i] * br[j];
        }
        __syncthreads();
    }

    if (logits_mode) {
        float bv[8];
        #pragma unroll
        for (int j = 0; j < 8; j++) bv[j] = bias[n0 + tx*8 + j];
        #pragma unroll
        for (int i = 0; i < 8; i++) {
            int m = m0 + ty*8 + i;
            int bb = m & 31, tt = m >> 5;          // hs rows are (t*32 + b)
            float* cp = C + ((size_t)bb * TT + tt) * N + n0 + tx*8;
            *(float4*)(cp)   = make_float4(acc[i][0]+bv[0], acc[i][1]+bv[1],
                                           acc[i][2]+bv[2], acc[i][3]+bv[3]);
            *(float4*)(cp+4) = make_float4(acc[i][4]+bv[4], acc[i][5]+bv[5],
                                           acc[i][6]+bv[6], acc[i][7]+bv[7]);
        }
    } else {
        #pragma unroll
        for (int i = 0; i < 8; i++) {
            float* cp = C + (size_t)(m0 + ty*8 + i) * N + n0 + tx*8;
            *(float4*)(cp)   = make_float4(acc[i][0], acc[i][1], acc[i][2], acc[i][3]);
            *(float4*)(cp+4) = make_float4(acc[i][4], acc[i][5], acc[i][6], acc[i][7]);
        }
    }
}

// ---------------- per-step kernels ----------------
__global__ void k_zero() {
    int i = blockIdx.x * 1024 + threadIdx.x;
    g_h[i] = 0.f; g_c[i] = 0.f;
}

// scores[b,s] = h[b] . M2[b,s,:]      grid (B, 7), 256 thr, 28 s per block
__global__ void k_scores() {
    __shared__ float hs[HH];
    int b = blockIdx.x, sc = blockIdx.y;
    int tid = threadIdx.x;
    for (int i = tid; i < HH/4; i += 256)
        ((float4*)hs)[i] = ((const float4*)(g_h + b*HH))[i];
    __syncthreads();
    int w = tid >> 5, lane = tid & 31;
    #pragma unroll
    for (int i = 0; i < 4; i++) {
        int sl = w + 8*i;
        if (sl < 28) {
            int s = sc*28 + sl;
            const float4* mrow = (const float4*)(g_M2 + ((size_t)b*SS + s) * HH);
            float acc = 0.f;
            #pragma unroll
            for (int kk = lane; kk < 256; kk += 32) {
                float4 m4 = mrow[kk];
                float4 h4 = ((const float4*)hs)[kk];
                acc += m4.x*h4.x + m4.y*h4.y + m4.z*h4.z + m4.w*h4.w;
            }
            #pragma unroll
            for (int o = 16; o; o >>= 1) acc += __shfl_xor_sync(0xffffffffu, acc, o);
            if (lane == 0) g_scores[b*SS + s] = acc;
        }
    }
}

// softmax over S + ctx[b,j] = sum_s w[s]*memory[b,s,j]   grid (B, 4), 256 thr
__global__ void k_ctx(const float* __restrict__ memory) {
    __shared__ float sw[256];
    __shared__ float red[256];
    int b = blockIdx.x;
    int tid = threadIdx.x;
    float v = (tid < SS) ? g_scores[b*SS + tid] : -1e30f;
    red[tid] = v; __syncthreads();
    for (int o = 128; o; o >>= 1) { if (tid < o) red[tid] = fmaxf(red[tid], red[tid+o]); __syncthreads(); }
    float mx = red[0]; __syncthreads();
    float e = (tid < SS) ? expf(v - mx) : 0.f;
    red[tid] = e; __syncthreads();
    for (int o = 128; o; o >>= 1) { if (tid < o) red[tid] += red[tid+o]; __syncthreads(); }
    float inv = 1.f / red[0];
    sw[tid] = e * inv;
    __syncthreads();
    int j = blockIdx.y * 256 + tid;
    const float* mp = memory + (size_t)b*SS*HH + j;
    float acc = 0.f;
    #pragma unroll 4
    for (int s = 0; s < SS; s++) acc += sw[s] * mp[(size_t)s*HH];
    g_ctx[b*HH + j] = acc;
}

// gate partials: ctx @ W_ih[:,1024:2048]^T + h @ W_hh^T, K split 8 ways
// grid (32 rowblocks, 8 ksplits), 256 thr. Thread: one gate row, 16 batches.
__global__ __launch_bounds__(256) void k_gates(
    const float* __restrict__ W_ih, const float* __restrict__ W_hh)
{
    __shared__ float xs[32][256];
    int tid = threadIdx.x;
    int rb = blockIdx.x, ks = blockIdx.y;
    int rl = tid & 127, bh = tid >> 7;
    const float* src = (ks < 4) ? g_ctx : g_h;
    int koff = (ks < 4) ? ks*256 : (ks-4)*256;
    int w = tid >> 5, lane = tid & 31;
    #pragma unroll
    for (int rep = 0; rep < 4; rep++) {
        int b = w + 8*rep;
        #pragma unroll
        for (int kk = lane*4; kk < 256; kk += 128)
            *(float4*)&xs[b][kk] = *(const float4*)&src[b*HH + koff + kk];
    }
    __syncthreads();
    int r = rb*128 + rl;
    const float* wrow = (ks < 4)
        ? (W_ih + (size_t)r*2048 + 1024 + ks*256)
        : (W_hh + (size_t)r*1024 + (ks-4)*256);
    float acc[16];
    #pragma unroll
    for (int i = 0; i < 16; i++) acc[i] = 0.f;
    #pragma unroll 2
    for (int k = 0; k < 256; k += 4) {
        float4 wv = *(const float4*)&wrow[k];
        #pragma unroll
        for (int b16 = 0; b16 < 16; b16++) {
            float4 xv = *(const float4*)&xs[bh*16 + b16][k];
            acc[b16] += wv.x * xv.x;
            acc[b16] += wv.y * xv.y;
            acc[b16] += wv.z * xv.z;
            acc[b16] += wv.w * xv.w;
        }
    }
    #pragma unroll
    for (int b16 = 0; b16 < 16; b16++)
        g_gp[(size_t)(ks*32 + bh*16 + b16) * RR + r] = acc[b16];
}

// LSTM cell pointwise: sum partials + E + biases, update h/c, store hs[t]
__global__ void k_cell(const float* __restrict__ b_ih, const float* __restrict__ b_hh, int t) {
    int b = blockIdx.x;
    int j = blockIdx.y * 256 + threadIdx.x;
    float gv[4];
    #pragma unroll
    for (int gi = 0; gi < 4; gi++) {
        int r = gi*1024 + j;
        float s = b_ih[r] + b_hh[r] + g_E[((size_t)b*TT + t) * RR + r];
        #pragma unroll
        for (int ks = 0; ks < 8; ks++) s += g_gp[(size_t)(ks*32 + b) * RR + r];
        gv[gi] = s;
    }
    float ig = 1.f / (1.f + expf(-gv[0]));
    float fg = 1.f / (1.f + expf(-gv[1]));
    float gg = tanhf(gv[2]);
    float og = 1.f / (1.f + expf(-gv[3]));
    float cprev = g_c[b*HH + j];
    float cn = fg * cprev + ig * gg;
    float hn = og * tanhf(cn);
    g_c[b*HH + j] = cn;
    g_h[b*HH + j] = hn;
    g_hs[((size_t)t*BB + b) * HH + j] = hn;
}

__global__ void k_copy_hc(float* __restrict__ out) {
    int i = blockIdx.x * 512 + threadIdx.x;   // 64*512 = 32768 = B*H
    const size_t OFF = (size_t)BB * TT * VV;
    out[OFF + i] = g_h[i];
    out[OFF + (size_t)BB*HH + i] = g_c[i];
}

// ---------------- launch ----------------
extern "C" void kernel_launch(void* const* d_in, const int* in_sizes, int n_in,
                              void* d_out, int out_size)
{
    const float* memory  = (const float*)d_in[0];
    const int*   captions= (const int*  )d_in[1];
    const float* emb     = (const float*)d_in[2];
    const float* attn_W  = (const float*)d_in[3];
    const float* W_ih    = (const float*)d_in[4];
    const float* W_hh    = (const float*)d_in[5];
    const float* b_ih    = (const float*)d_in[6];
    const float* b_hh    = (const float*)d_in[7];
    const float* W_out   = (const float*)d_in[8];
    const float* b_out   = (const float*)d_in[9];
    float* out = (float*)d_out;

    static float *pM2 = nullptr, *pE = nullptr, *pHS = nullptr;
    if (!pM2) {   // resolved on the (uncaptured) correctness call; pure address lookup
        cudaGetSymbolAddress((void**)&pM2, g_M2);
        cudaGetSymbolAddress((void**)&pE,  g_E);
        cudaGetSymbolAddress((void**)&pHS, g_hs);
    }

    k_zero<<<32, 1024>>>();

    // M2 = memory @ attn_W            [6272,1024] x [1024,1024]
    sgemm_nn<<<dim3(HH/128, (BB*SS)/128), 256>>>(memory, attn_W, pM2, BB*SS, HH, HH);

    // E = emb[captions] @ W_ih[:, :H]^T   [2048,1024] x [4096,1024(ld 2048)]^T
    sgemm_nt<<<dim3(RR/128, (BB*TT)/128), 256>>>(nullptr, W_ih, pE, BB*TT, RR, HH,
                                                 2048, captions, emb, nullptr, 0);

    for (int t = 0; t < TT; t++) {
        k_scores<<<dim3(BB, 7), 256>>>();
        k_ctx   <<<dim3(BB, 4), 256>>>(memory);
        k_gates <<<dim3(32, 8), 256>>>(W_ih, W_hh);
        k_cell  <<<dim3(BB, 4), 256>>>(b_ih, b_hh, t);
    }

    // logits = hs @ W_out^T + b_out   [2048,1024] x [32000,1024]^T, remapped (b,t)
    sgemm_nt<<<dim3(VV/128, (BB*TT)/128), 256>>>(pHS, W_out, out, BB*TT, VV, HH,
                                                 HH, nullptr, nullptr, b_out, 1);

    k_copy_hc<<<64, 512>>>(out);
}

// round 3
// speedup vs baseline: 1.2775x; 1.2775x over previous
#include <cuda_runtime.h>
#include <cstdint>
#include <math.h>

#define BB 32
#define SS 196
#define TT 64
#define HH 1024
#define VV 32000
#define RR 4096   // 4*H
#define PADW 8    // smem pad so LDS fragment reads are conflict-free

// ---------------- scratch (static device globals; no allocations) ----------------
__device__ float g_M2[(size_t)BB*SS*HH];   // memory @ attn_W      [B*S, H]
__device__ float g_E [(size_t)BB*TT*RR];   // emb gates precompute [B*T, 4H]
__device__ float g_hs[(size_t)TT*BB*HH];   // h_t history          [rows = t*32+b, H]
__device__ float g_gp[(size_t)8*BB*RR];    // gate partials        [KS=8, B, 4H]
__device__ float g_h [BB*HH];
__device__ float g_c [BB*HH];
__device__ float g_ctx[BB*HH];

// ---------------- tf32 helpers ----------------
__device__ __forceinline__ float f2tf32(float x) {
    uint32_t u; asm("cvt.rna.tf32.f32 %0, %1;" : "=r"(u) : "f"(x));
    return __uint_as_float(u);
}
__device__ __forceinline__ void mma_op(float* c, const uint32_t* a, const uint32_t* b) {
    asm volatile(
        "mma.sync.aligned.m16n8k8.row.col.f32.tf32.tf32.f32 "
        "{%0,%1,%2,%3},{%4,%5,%6,%7},{%8,%9},{%0,%1,%2,%3};"
        : "+f"(c[0]), "+f"(c[1]), "+f"(c[2]), "+f"(c[3])
        : "r"(a[0]), "r"(a[1]), "r"(a[2]), "r"(a[3]), "r"(b[0]), "r"(b[1]));
}

// ---------------- tf32 tensor-core GEMM ----------------
// C[M,N] = A[M,K] @ B, fp32 in/out, tf32 mma, fp32 accumulate.
// mode 0: B = Bt[N,ldb] used transposed (C += A·Bt^T)          (E precompute)
// mode 1: same as 0, plus bias[n] and logits row remap:
//         A-row m encodes (t*32+b) -> C row (b*T + t)          (logits)
// mode 2: B = Bm[K,N] row-major (ldb = N)                      (M2 = memory@attn_W)
// gatherIdx != null: A row m taken from gatherTab + gatherIdx[m]*K
__global__ __launch_bounds__(256, 2) void mma_gemm(
    const float* __restrict__ A, const float* __restrict__ Bsrc,
    float* __restrict__ C, int M, int N, int K, int ldb,
    const int* __restrict__ gatherIdx, const float* __restrict__ gatherTab,
    const float* __restrict__ bias, int mode)
{
    __shared__ float As[16][128 + PADW];   // As[k][m]
    __shared__ float Bs[16][128 + PADW];   // Bs[k][n]
    int tid = threadIdx.x;
    int n0 = blockIdx.x * 128, m0 = blockIdx.y * 128;
    int warp = tid >> 5, lane = tid & 31;
    int wm = warp >> 1, wn = warp & 1;     // 4x2 warp grid, warp tile 32x64
    int grp = lane >> 2, tg = lane & 3;

    float acc[2][8][4] = {};

    // per-thread A source rows (2 loads of float4 per BK=16 tile)
    const float* arow[2];
    int ac4[2];
    #pragma unroll
    for (int it = 0; it < 2; it++) {
        int idx = tid + it * 256;
        int r = idx >> 2; ac4[it] = (idx & 3) * 4;
        arow[it] = gatherIdx ? (gatherTab + (size_t)gatherIdx[m0 + r] * K)
                             : (A + (size_t)(m0 + r) * K);
    }

    for (int k0 = 0; k0 < K; k0 += 16) {
        // ---- load A tile (transpose to As[k][m], tf32-round) ----
        #pragma unroll
        for (int it = 0; it < 2; it++) {
            int idx = tid + it * 256;
            int r = idx >> 2;
            float4 v = *(const float4*)(arow[it] + k0 + ac4[it]);
            As[ac4[it]+0][r] = f2tf32(v.x); As[ac4[it]+1][r] = f2tf32(v.y);
            As[ac4[it]+2][r] = f2tf32(v.z); As[ac4[it]+3][r] = f2tf32(v.w);
        }
        // ---- load B tile into Bs[k][n] ----
        if (mode == 2) {
            #pragma unroll
            for (int it = 0; it < 2; it++) {
                int idx = tid + it * 256;
                int r = idx >> 5, c4 = (idx & 31) * 4;   // r = k row, c4 = n offset
                float4 v = *(const float4*)(Bsrc + (size_t)(k0 + r) * ldb + n0 + c4);
                Bs[r][c4+0] = f2tf32(v.x); Bs[r][c4+1] = f2tf32(v.y);
                Bs[r][c4+2] = f2tf32(v.z); Bs[r][c4+3] = f2tf32(v.w);
            }
        } else {
            #pragma unroll
            for (int it = 0; it < 2; it++) {
                int idx = tid + it * 256;
                int r = idx >> 2, c4 = (idx & 3) * 4;    // r = n row, c4 = k offset
                float4 v = *(const float4*)(Bsrc + (size_t)(n0 + r) * ldb + k0 + c4);
                Bs[c4+0][r] = f2tf32(v.x); Bs[c4+1][r] = f2tf32(v.y);
                Bs[c4+2][r] = f2tf32(v.z); Bs[c4+3][r] = f2tf32(v.w);
            }
        }
        __syncthreads();

        // ---- 2 x k8 mma steps ----
        #pragma unroll
        for (int ks = 0; ks < 2; ks++) {
            int kb = ks * 8;
            uint32_t af[2][4], bf[8][2];
            #pragma unroll
            for (int mt = 0; mt < 2; mt++) {
                int r = wm * 32 + mt * 16 + grp;
                af[mt][0] = __float_as_uint(As[kb+tg  ][r  ]);
                af[mt][1] = __float_as_uint(As[kb+tg  ][r+8]);
                af[mt][2] = __float_as_uint(As[kb+tg+4][r  ]);
                af[mt][3] = __float_as_uint(As[kb+tg+4][r+8]);
            }
            #pragma unroll
            for (int nt = 0; nt < 8; nt++) {
                int cix = wn * 64 + nt * 8 + grp;
                bf[nt][0] = __float_as_uint(Bs[kb+tg  ][cix]);
                bf[nt][1] = __float_as_uint(Bs[kb+tg+4][cix]);
            }
            #pragma unroll
            for (int mt = 0; mt < 2; mt++)
                #pragma unroll
                for (int nt = 0; nt < 8; nt++)
                    mma_op(acc[mt][nt], af[mt], bf[nt]);
        }
        __syncthreads();
    }

    // ---- epilogue ----
    #pragma unroll
    for (int mt = 0; mt < 2; mt++) {
        int mg = m0 + wm * 32 + mt * 16 + grp;    // rows mg and mg+8
        #pragma unroll
        for (int nt = 0; nt < 8; nt++) {
            int ng = n0 + wn * 64 + nt * 8 + tg * 2;
            float* a4 = acc[mt][nt];
            if (mode == 1) {
                float b0 = __ldg(bias + ng), b1 = __ldg(bias + ng + 1);
                int m1 = mg, m2 = mg + 8;
                size_t r1 = ((size_t)(m1 & 31) * TT + (m1 >> 5)) * N;
                size_t r2 = ((size_t)(m2 & 31) * TT + (m2 >> 5)) * N;
                *(float2*)(C + r1 + ng) = make_float2(a4[0] + b0, a4[1] + b1);
                *(float2*)(C + r2 + ng) = make_float2(a4[2] + b0, a4[3] + b1);
            } else {
                *(float2*)(C + (size_t)mg * N + ng)       = make_float2(a4[0], a4[1]);
                *(float2*)(C + (size_t)(mg + 8) * N + ng) = make_float2(a4[2], a4[3]);
            }
        }
    }
}

// ---------------- per-step kernels ----------------
__global__ void k_zero() {
    int i = blockIdx.x * 1024 + threadIdx.x;
    g_h[i] = 0.f; g_c[i] = 0.f;
}

// fused: scores (h . M2 rows) -> softmax -> ctx.  grid (B), 512 thr
__global__ __launch_bounds__(512) void k_attn(const float* __restrict__ memory) {
    __shared__ float hsm[HH];
    __shared__ float sw[256];
    __shared__ float red[512];
    int b = blockIdx.x, tid = threadIdx.x;
    for (int i = tid; i < HH/4; i += 512)
        ((float4*)hsm)[i] = ((const float4*)(g_h + b*HH))[i];
    __syncthreads();

    int w = tid >> 5, lane = tid & 31;
    for (int s = w; s < SS; s += 16) {
        const float4* mrow = (const float4*)(g_M2 + ((size_t)b*SS + s) * HH);
        float a = 0.f;
        #pragma unroll
        for (int kk = lane; kk < 256; kk += 32) {
            float4 m4 = mrow[kk];
            float4 h4 = ((const float4*)hsm)[kk];
            a += m4.x*h4.x + m4.y*h4.y + m4.z*h4.z + m4.w*h4.w;
        }
        #pragma unroll
        for (int o = 16; o; o >>= 1) a += __shfl_xor_sync(0xffffffffu, a, o);
        if (!lane) sw[s] = a;
    }
    __syncthreads();

    float v = (tid < SS) ? sw[tid] : -1e30f;
    red[tid] = v; __syncthreads();
    for (int o = 256; o; o >>= 1) { if (tid < o) red[tid] = fmaxf(red[tid], red[tid+o]); __syncthreads(); }
    float mx = red[0]; __syncthreads();
    float e = (tid < SS) ? expf(v - mx) : 0.f;
    red[tid] = e; __syncthreads();
    for (int o = 256; o; o >>= 1) { if (tid < o) red[tid] += red[tid+o]; __syncthreads(); }
    float inv = 1.f / red[0];
    if (tid < 256) sw[tid] = (tid < SS) ? e * inv : 0.f;
    __syncthreads();

    int j = tid * 2;
    const float* mp = memory + (size_t)b*SS*HH + j;
    float a0 = 0.f, a1 = 0.f;
    #pragma unroll 4
    for (int s = 0; s < SS; s++) {
        float2 m2 = *(const float2*)(mp + (size_t)s * HH);
        float wv = sw[s];
        a0 += wv * m2.x; a1 += wv * m2.y;
    }
    *(float2*)(g_ctx + b*HH + j) = make_float2(a0, a1);
}

// gate partials: ctx @ W_ih[:,1024:2048]^T + h @ W_hh^T, K split 8 ways
__global__ __launch_bounds__(256) void k_gates(
    const float* __restrict__ W_ih, const float* __restrict__ W_hh)
{
    __shared__ float xs[32][256];
    int tid = threadIdx.x;
    int rb = blockIdx.x, ks = blockIdx.y;
    int rl = tid & 127, bh = tid >> 7;
    const float* src = (ks < 4) ? g_ctx : g_h;
    int koff = (ks < 4) ? ks*256 : (ks-4)*256;
    int w = tid >> 5, lane = tid & 31;
    #pragma unroll
    for (int rep = 0; rep < 4; rep++) {
        int b = w + 8*rep;
        #pragma unroll
        for (int kk = lane*4; kk < 256; kk += 128)
            *(float4*)&xs[b][kk] = *(const float4*)&src[b*HH + koff + kk];
    }
    __syncthreads();
    int r = rb*128 + rl;
    const float* wrow = (ks < 4)
        ? (W_ih + (size_t)r*2048 + 1024 + ks*256)
        : (W_hh + (size_t)r*1024 + (ks-4)*256);
    float acc[16];
    #pragma unroll
    for (int i = 0; i < 16; i++) acc[i] = 0.f;
    #pragma unroll 2
    for (int k = 0; k < 256; k += 4) {
        float4 wv = *(const float4*)&wrow[k];
        #pragma unroll
        for (int b16 = 0; b16 < 16; b16++) {
            float4 xv = *(const float4*)&xs[bh*16 + b16][k];
            acc[b16] += wv.x * xv.x;
            acc[b16] += wv.y * xv.y;
            acc[b16] += wv.z * xv.z;
            acc[b16] += wv.w * xv.w;
        }
    }
    #pragma unroll
    for (int b16 = 0; b16 < 16; b16++)
        g_gp[(size_t)(ks*32 + bh*16 + b16) * RR + r] = acc[b16];
}

// LSTM cell pointwise
__global__ void k_cell(const float* __restrict__ b_ih, const float* __restrict__ b_hh, int t) {
    int b = blockIdx.x;
    int j = blockIdx.y * 256 + threadIdx.x;
    float gv[4];
    #pragma unroll
    for (int gi = 0; gi < 4; gi++) {
        int r = gi*1024 + j;
        float s = b_ih[r] + b_hh[r] + g_E[((size_t)b*TT + t) * RR + r];
        #pragma unroll
        for (int ks = 0; ks < 8; ks++) s += g_gp[(size_t)(ks*32 + b) * RR + r];
        gv[gi] = s;
    }
    float ig = 1.f / (1.f + expf(-gv[0]));
    float fg = 1.f / (1.f + expf(-gv[1]));
    float gg = tanhf(gv[2]);
    float og = 1.f / (1.f + expf(-gv[3]));
    float cprev = g_c[b*HH + j];
    float cn = fg * cprev + ig * gg;
    float hn = og * tanhf(cn);
    g_c[b*HH + j] = cn;
    g_h[b*HH + j] = hn;
    g_hs[((size_t)t*BB + b) * HH + j] = hn;
}

__global__ void k_copy_hc(float* __restrict__ out) {
    int i = blockIdx.x * 512 + threadIdx.x;
    const size_t OFF = (size_t)BB * TT * VV;
    out[OFF + i] = g_h[i];
    out[OFF + (size_t)BB*HH + i] = g_c[i];
}

// ---------------- launch ----------------
extern "C" void kernel_launch(void* const* d_in, const int* in_sizes, int n_in,
                              void* d_out, int out_size)
{
    const float* memory  = (const float*)d_in[0];
    const int*   captions= (const int*  )d_in[1];
    const float* emb     = (const float*)d_in[2];
    const float* attn_W  = (const float*)d_in[3];
    const float* W_ih    = (const float*)d_in[4];
    const float* W_hh    = (const float*)d_in[5];
    const float* b_ih    = (const float*)d_in[6];
    const float* b_hh    = (const float*)d_in[7];
    const float* W_out   = (const float*)d_in[8];
    const float* b_out   = (const float*)d_in[9];
    float* out = (float*)d_out;

    static float *pM2 = nullptr, *pE = nullptr, *pHS = nullptr;
    if (!pM2) {
        cudaGetSymbolAddress((void**)&pM2, g_M2);
        cudaGetSymbolAddress((void**)&pE,  g_E);
        cudaGetSymbolAddress((void**)&pHS, g_hs);
    }

    k_zero<<<32, 1024>>>();

    // M2 = memory @ attn_W (mode 2, NN)     [6272,1024] x [1024,1024]
    mma_gemm<<<dim3(HH/128, (BB*SS)/128), 256>>>(
        memory, attn_W, pM2, BB*SS, HH, HH, HH,
        nullptr, nullptr, nullptr, 2);

    // E = emb[captions] @ W_ih[:, :H]^T (mode 0, NT + gather) [2048 x 4096], K=1024
    mma_gemm<<<dim3(RR/128, (BB*TT)/128), 256>>>(
        nullptr, W_ih, pE, BB*TT, RR, HH, 2048,
        captions, emb, nullptr, 0);

    for (int t = 0; t < TT; t++) {
        k_attn <<<BB, 512>>>(memory);
        k_gates<<<dim3(32, 8), 256>>>(W_ih, W_hh);
        k_cell <<<dim3(BB, 4), 256>>>(b_ih, b_hh, t);
    }

    // logits = hs @ W_out^T + b_out (mode 1)  [2048 x 32000], K=1024
    mma_gemm<<<dim3(VV/128, (BB*TT)/128), 256>>>(
        pHS, W_out, out, BB*TT, VV, HH, HH,
        nullptr, nullptr, b_out, 1);

    k_copy_hc<<<64, 512>>>(out);
}

// round 4
// speedup vs baseline: 1.6810x; 1.3159x over previous
#include <cuda_runtime.h>
#include <cstdint>
#include <math.h>

#define BB 32
#define SS 196
#define TT 64
#define HH 1024
#define VV 32000
#define RR 4096   // 4*H
#define PADW 8
#define NB 148    // persistent grid size (1 block per SM)

// ---------------- scratch ----------------
__device__ float g_M2[(size_t)BB*SS*HH];
__device__ float g_E [(size_t)BB*TT*RR];
__device__ float g_hs[(size_t)TT*BB*HH];   // rows = t*32+b
__device__ float g_gp[(size_t)8*BB*RR];
__device__ float g_h [BB*HH];
__device__ float g_c [BB*HH];
__device__ float g_ctx[BB*HH];
__device__ float g_scores[BB*SS];
__device__ unsigned g_bar;

// ---------------- tf32 helpers ----------------
__device__ __forceinline__ float f2tf32(float x) {
    uint32_t u; asm("cvt.rna.tf32.f32 %0, %1;" : "=r"(u) : "f"(x));
    return __uint_as_float(u);
}
__device__ __forceinline__ void mma_op(float* c, const uint32_t* a, const uint32_t* b) {
    asm volatile(
        "mma.sync.aligned.m16n8k8.row.col.f32.tf32.tf32.f32 "
        "{%0,%1,%2,%3},{%4,%5,%6,%7},{%8,%9},{%0,%1,%2,%3};"
        : "+f"(c[0]), "+f"(c[1]), "+f"(c[2]), "+f"(c[3])
        : "r"(a[0]), "r"(a[1]), "r"(a[2]), "r"(a[3]), "r"(b[0]), "r"(b[1]));
}

// ---------------- tf32 tensor-core GEMM (unchanged from R3) ----------------
__global__ __launch_bounds__(256, 2) void mma_gemm(
    const float* __restrict__ A, const float* __restrict__ Bsrc,
    float* __restrict__ C, int M, int N, int K, int ldb,
    const int* __restrict__ gatherIdx, const float* __restrict__ gatherTab,
    const float* __restrict__ bias, int mode)
{
    __shared__ float As[16][128 + PADW];
    __shared__ float Bs[16][128 + PADW];
    int tid = threadIdx.x;
    int n0 = blockIdx.x * 128, m0 = blockIdx.y * 128;
    int warp = tid >> 5, lane = tid & 31;
    int wm = warp >> 1, wn = warp & 1;
    int grp = lane >> 2, tg = lane & 3;

    float acc[2][8][4] = {};

    const float* arow[2];
    int ac4[2];
    #pragma unroll
    for (int it = 0; it < 2; it++) {
        int idx = tid + it * 256;
        int r = idx >> 2; ac4[it] = (idx & 3) * 4;
        arow[it] = gatherIdx ? (gatherTab + (size_t)gatherIdx[m0 + r] * K)
                             : (A + (size_t)(m0 + r) * K);
    }

    for (int k0 = 0; k0 < K; k0 += 16) {
        #pragma unroll
        for (int it = 0; it < 2; it++) {
            int idx = tid + it * 256;
            int r = idx >> 2;
            float4 v = *(const float4*)(arow[it] + k0 + ac4[it]);
            As[ac4[it]+0][r] = f2tf32(v.x); As[ac4[it]+1][r] = f2tf32(v.y);
            As[ac4[it]+2][r] = f2tf32(v.z); As[ac4[it]+3][r] = f2tf32(v.w);
        }
        if (mode == 2) {
            #pragma unroll
            for (int it = 0; it < 2; it++) {
                int idx = tid + it * 256;
                int r = idx >> 5, c4 = (idx & 31) * 4;
                float4 v = *(const float4*)(Bsrc + (size_t)(k0 + r) * ldb + n0 + c4);
                Bs[r][c4+0] = f2tf32(v.x); Bs[r][c4+1] = f2tf32(v.y);
                Bs[r][c4+2] = f2tf32(v.z); Bs[r][c4+3] = f2tf32(v.w);
            }
        } else {
            #pragma unroll
            for (int it = 0; it < 2; it++) {
                int idx = tid + it * 256;
                int r = idx >> 2, c4 = (idx & 3) * 4;
                float4 v = *(const float4*)(Bsrc + (size_t)(n0 + r) * ldb + k0 + c4);
                Bs[c4+0][r] = f2tf32(v.x); Bs[c4+1][r] = f2tf32(v.y);
                Bs[c4+2][r] = f2tf32(v.z); Bs[c4+3][r] = f2tf32(v.w);
            }
        }
        __syncthreads();

        #pragma unroll
        for (int ks = 0; ks < 2; ks++) {
            int kb = ks * 8;
            uint32_t af[2][4], bf[8][2];
            #pragma unroll
            for (int mt = 0; mt < 2; mt++) {
                int r = wm * 32 + mt * 16 + grp;
                af[mt][0] = __float_as_uint(As[kb+tg  ][r  ]);
                af[mt][1] = __float_as_uint(As[kb+tg  ][r+8]);
                af[mt][2] = __float_as_uint(As[kb+tg+4][r  ]);
                af[mt][3] = __float_as_uint(As[kb+tg+4][r+8]);
            }
            #pragma unroll
            for (int nt = 0; nt < 8; nt++) {
                int cix = wn * 64 + nt * 8 + grp;
                bf[nt][0] = __float_as_uint(Bs[kb+tg  ][cix]);
                bf[nt][1] = __float_as_uint(Bs[kb+tg+4][cix]);
            }
            #pragma unroll
            for (int mt = 0; mt < 2; mt++)
                #pragma unroll
                for (int nt = 0; nt < 8; nt++)
                    mma_op(acc[mt][nt], af[mt], bf[nt]);
        }
        __syncthreads();
    }

    #pragma unroll
    for (int mt = 0; mt < 2; mt++) {
        int mg = m0 + wm * 32 + mt * 16 + grp;
        #pragma unroll
        for (int nt = 0; nt < 8; nt++) {
            int ng = n0 + wn * 64 + nt * 8 + tg * 2;
            float* a4 = acc[mt][nt];
            if (mode == 1) {
                float b0 = __ldg(bias + ng), b1 = __ldg(bias + ng + 1);
                size_t r1 = ((size_t)(mg & 31) * TT + (mg >> 5)) * N;
                size_t r2 = ((size_t)((mg+8) & 31) * TT + ((mg+8) >> 5)) * N;
                *(float2*)(C + r1 + ng) = make_float2(a4[0] + b0, a4[1] + b1);
                *(float2*)(C + r2 + ng) = make_float2(a4[2] + b0, a4[3] + b1);
            } else {
                *(float2*)(C + (size_t)mg * N + ng)       = make_float2(a4[0], a4[1]);
                *(float2*)(C + (size_t)(mg + 8) * N + ng) = make_float2(a4[2], a4[3]);
            }
        }
    }
}

// ---------------- persistent recurrence ----------------
__device__ __forceinline__ void gridbar(unsigned target) {
    __syncthreads();
    if (threadIdx.x == 0) {
        __threadfence();                    // release + L1 invalidate (gpu scope)
        atomicAdd(&g_bar, 1u);
        while (*(volatile unsigned*)&g_bar < target) { }
        __threadfence();                    // acquire side: invalidate stale L1
    }
    __syncthreads();
}

__global__ __launch_bounds__(1024, 1) void k_recur(
    const float* __restrict__ memory,
    const float* __restrict__ W_ih, const float* __restrict__ W_hh,
    const float* __restrict__ b_ih, const float* __restrict__ b_hh)
{
    extern __shared__ float smem[];
    // layout: xs[4][32][256] = 32768 floats | sw[256] | red[256] | part[1024]
    float* sw  = smem + 32768;
    float* red = smem + 32768 + 256;
    float* part= smem + 32768 + 512;

    const int tid = threadIdx.x;
    const int bid = blockIdx.x;
    const int w = tid >> 5, lane = tid & 31;
    unsigned tgt = NB;

    for (int t = 0; t < TT; t++) {
        // ---------- Phase A: scores[b,s] = h[b] . M2[b,s,:] ----------
        {
            int gw = bid * 32 + w;                 // 0..4735
            for (int p = gw; p < BB * SS; p += NB * 32) {
                int b = p / SS;
                const float4* m4 = (const float4*)(g_M2 + (size_t)p * HH);
                const float4* h4 = (const float4*)(g_h + b * HH);
                float a = 0.f;
                #pragma unroll
                for (int i = 0; i < 8; i++) {
                    int f = i * 32 + lane;
                    float4 mv = m4[f], hv = h4[f];
                    a += mv.x*hv.x + mv.y*hv.y + mv.z*hv.z + mv.w*hv.w;
                }
                #pragma unroll
                for (int o = 16; o; o >>= 1) a += __shfl_xor_sync(0xffffffffu, a, o);
                if (!lane) g_scores[p] = a;
            }
        }
        gridbar(tgt); tgt += NB;

        // ---------- Phase B: softmax + ctx ----------
        if (bid < 128) {
            int b = bid >> 2, jblk = bid & 3;
            float v = -1e30f;
            if (tid < 256) {
                v = (tid < SS) ? g_scores[b * SS + tid] : -1e30f;
                red[tid] = v;
            }
            __syncthreads();
            for (int o = 128; o; o >>= 1) { if (tid < o) red[tid] = fmaxf(red[tid], red[tid+o]); __syncthreads(); }
            float mx = red[0]; __syncthreads();
            float e = 0.f;
            if (tid < 256) { e = (tid < SS) ? expf(v - mx) : 0.f; red[tid] = e; }
            __syncthreads();
            for (int o = 128; o; o >>= 1) { if (tid < o) red[tid] += red[tid+o]; __syncthreads(); }
            float inv = 1.f / red[0];
            if (tid < 256) sw[tid] = e * inv;
            __syncthreads();

            int jj = tid & 255, sp = tid >> 8;
            int j = jblk * 256 + jj;
            const float* mp = memory + ((size_t)b * SS + sp * 49) * HH + j;
            float acc = 0.f;
            #pragma unroll 7
            for (int s = 0; s < 49; s++)
                acc += sw[sp * 49 + s] * mp[(size_t)s * HH];
            part[sp * 256 + jj] = acc;
            __syncthreads();
            if (tid < 256)
                g_ctx[b * HH + j] = part[jj] + part[256+jj] + part[512+jj] + part[768+jj];
        }
        gridbar(tgt); tgt += NB;

        // ---------- Phase C: gate partials ----------
        {
            int g = tid >> 8;                     // group 0..3
            int t256 = tid & 255;
            int su = bid + NB * g;                // 0..591
            if (su < 256) {
                int rb = su >> 3, ks = su & 7;
                float* xs = smem + g * (32 * 256);
                const float* src = (ks < 4) ? g_ctx : g_h;
                int koff = (ks < 4) ? ks * 256 : (ks - 4) * 256;
                int w8 = t256 >> 5, l = t256 & 31;
                #pragma unroll
                for (int rep = 0; rep < 4; rep++) {
                    int bb = w8 + 8 * rep;
                    #pragma unroll
                    for (int kk = l * 4; kk < 256; kk += 128)
                        *(float4*)&xs[bb * 256 + kk] = *(const float4*)&src[bb * HH + koff + kk];
                }
                asm volatile("bar.sync %0, %1;" :: "r"(g + 1), "r"(256) : "memory");

                int rl = t256 & 127, bh = t256 >> 7;
                int r = rb * 128 + rl;
                const float* wrow = (ks < 4)
                    ? (W_ih + (size_t)r * 2048 + 1024 + ks * 256)
                    : (W_hh + (size_t)r * 1024 + (ks - 4) * 256);
                float acc[16];
                #pragma unroll
                for (int i = 0; i < 16; i++) acc[i] = 0.f;
                #pragma unroll 2
                for (int k = 0; k < 256; k += 4) {
                    float4 wv = *(const float4*)&wrow[k];
                    #pragma unroll
                    for (int b16 = 0; b16 < 16; b16++) {
                        float4 xv = *(const float4*)&xs[(bh * 16 + b16) * 256 + k];
                        acc[b16] += wv.x * xv.x;
                        acc[b16] += wv.y * xv.y;
                        acc[b16] += wv.z * xv.z;
                        acc[b16] += wv.w * xv.w;
                    }
                }
                #pragma unroll
                for (int b16 = 0; b16 < 16; b16++)
                    g_gp[(size_t)(ks * 32 + bh * 16 + b16) * RR + r] = acc[b16];
            }
        }
        gridbar(tgt); tgt += NB;

        // ---------- Phase D: LSTM cell ----------
        {
            int idx = bid * 1024 + tid;
            if (idx < BB * HH) {
                int b = idx >> 10, j = idx & 1023;
                float gv[4];
                #pragma unroll
                for (int gi = 0; gi < 4; gi++) {
                    int r = gi * 1024 + j;
                    float s = b_ih[r] + b_hh[r] + g_E[((size_t)b * TT + t) * RR + r];
                    #pragma unroll
                    for (int ks = 0; ks < 8; ks++) s += g_gp[(size_t)(ks * 32 + b) * RR + r];
                    gv[gi] = s;
                }
                float ig = 1.f / (1.f + expf(-gv[0]));
                float fg = 1.f / (1.f + expf(-gv[1]));
                float gg = tanhf(gv[2]);
                float og = 1.f / (1.f + expf(-gv[3]));
                float cn = fg * g_c[idx] + ig * gg;
                float hn = og * tanhf(cn);
                g_c[idx] = cn;
                g_h[idx] = hn;
                g_hs[((size_t)t * BB + b) * HH + j] = hn;
            }
        }
        gridbar(tgt); tgt += NB;
    }
}

// ---------------- small kernels ----------------
__global__ void k_zero() {
    int i = blockIdx.x * 1024 + threadIdx.x;
    g_h[i] = 0.f; g_c[i] = 0.f;
    if (i == 0) g_bar = 0u;
}

__global__ void k_copy_hc(float* __restrict__ out) {
    int i = blockIdx.x * 512 + threadIdx.x;
    const size_t OFF = (size_t)BB * TT * VV;
    out[OFF + i] = g_h[i];
    out[OFF + (size_t)BB*HH + i] = g_c[i];
}

// ---------------- launch ----------------
extern "C" void kernel_launch(void* const* d_in, const int* in_sizes, int n_in,
                              void* d_out, int out_size)
{
    const float* memory  = (const float*)d_in[0];
    const int*   captions= (const int*  )d_in[1];
    const float* emb     = (const float*)d_in[2];
    const float* attn_W  = (const float*)d_in[3];
    const float* W_ih    = (const float*)d_in[4];
    const float* W_hh    = (const float*)d_in[5];
    const float* b_ih    = (const float*)d_in[6];
    const float* b_hh    = (const float*)d_in[7];
    const float* W_out   = (const float*)d_in[8];
    const float* b_out   = (const float*)d_in[9];
    float* out = (float*)d_out;

    const int SMEM_RECUR = (32768 + 256 + 256 + 1024) * 4;   // 137216 B

    static float *pM2 = nullptr, *pE = nullptr, *pHS = nullptr;
    if (!pM2) {
        cudaGetSymbolAddress((void**)&pM2, g_M2);
        cudaGetSymbolAddress((void**)&pE,  g_E);
        cudaGetSymbolAddress((void**)&pHS, g_hs);
        cudaFuncSetAttribute(k_recur, cudaFuncAttributeMaxDynamicSharedMemorySize, SMEM_RECUR);
    }

    k_zero<<<32, 1024>>>();

    // M2 = memory @ attn_W
    mma_gemm<<<dim3(HH/128, (BB*SS)/128), 256>>>(
        memory, attn_W, pM2, BB*SS, HH, HH, HH,
        nullptr, nullptr, nullptr, 2);

    // E = emb[captions] @ W_ih[:, :H]^T
    mma_gemm<<<dim3(RR/128, (BB*TT)/128), 256>>>(
        nullptr, W_ih, pE, BB*TT, RR, HH, 2048,
        captions, emb, nullptr, 0);

    // whole recurrence: ONE persistent launch
    k_recur<<<NB, 1024, SMEM_RECUR>>>(memory, W_ih, W_hh, b_ih, b_hh);

    // logits = hs @ W_out^T + b_out
    mma_gemm<<<dim3(VV/128, (BB*TT)/128), 256>>>(
        pHS, W_out, out, BB*TT, VV, HH, HH,
        nullptr, nullptr, b_out, 1);

    k_copy_hc<<<64, 512>>>(out);
}